// round 1
// baseline (speedup 1.0000x reference)
#include <cuda_runtime.h>
#include <cuda_bf16.h>
#include <math_constants.h>

// Problem constants
#define NUM_CODES   2560
#define DIM         128
#define N_TOKENS    65536          // 16 * 64 * 64
#define TOT_ELEMS   8388608        // 16 * 128 * 64 * 64
#define TOK_PER_BLK 64
#define CODES_PER_CHUNK 256
#define N_CHUNKS    (NUM_CODES / CODES_PER_CHUNK)   // 10
#define ZSTRIDE     132            // padded row stride (words); 132*4=528B = 33*16B aligned

// scratch (static device globals are the allowed scratch mechanism)
__device__ float  g_enorm[NUM_CODES];
__device__ double g_s1;   // sum (z_q - z)^2   (fp32-squared, accumulated in double)
__device__ double g_s3;   // sum (batch - out)^2

// ---------------- packed f32x2 helpers ----------------
__device__ __forceinline__ unsigned long long ffma2(unsigned long long a,
                                                    unsigned long long b,
                                                    unsigned long long c) {
    unsigned long long d;
    asm("fma.rn.f32x2 %0, %1, %2, %3;" : "=l"(d) : "l"(a), "l"(b), "l"(c));
    return d;
}
__device__ __forceinline__ void unpack2(unsigned long long p, float& lo, float& hi) {
    asm("mov.b64 {%0, %1}, %2;" : "=f"(lo), "=f"(hi) : "l"(p));
}

// ---------------- prep: enorm + zero loss accumulators ----------------
__global__ void vq_prep(const float* __restrict__ w) {
    if (blockIdx.x == 0 && threadIdx.x == 0) { g_s1 = 0.0; g_s3 = 0.0; }
    int gw   = (blockIdx.x * blockDim.x + threadIdx.x) >> 5;   // global warp id = code
    int lane = threadIdx.x & 31;
    if (gw < NUM_CODES) {
        const float* row = w + (size_t)gw * DIM;
        float s = 0.0f;
        #pragma unroll
        for (int k = lane; k < DIM; k += 32) {
            float v = row[k];
            s = __fadd_rn(s, __fmul_rn(v, v));
        }
        #pragma unroll
        for (int off = 16; off > 0; off >>= 1)
            s += __shfl_xor_sync(0xffffffffu, s, off);
        if (lane == 0) g_enorm[gw] = s;
    }
}

// ---------------- main kernel ----------------
// grid: N_TOKENS/64 = 1024 blocks, 256 threads
// smem layout (floats):
//   zs [64][132]      : 8448
//   ws [256][132]     : 33792   (reused for argmin reduction + double loss reduce)
//   zn [64], en[256], inds[64]
__global__ void __launch_bounds__(256, 1)
vq_main(const float* __restrict__ batch, const float* __restrict__ w,
        float* __restrict__ out) {
    extern __shared__ float sm[];
    float* zs   = sm;                          // 64*132
    float* ws   = sm + TOK_PER_BLK * ZSTRIDE;  // 256*132
    float* zn   = ws + CODES_PER_CHUNK * ZSTRIDE;  // 64
    float* en   = zn + TOK_PER_BLK;                // 256
    int*   inds = (int*)(en + CODES_PER_CHUNK);    // 64

    // reduction scratch aliases ws (only used after compute loop / between syncs)
    float* rv = ws;                   // [64][32]
    int*   ri = (int*)(ws + 2048);    // [64][32]

    const int tid = threadIdx.x;
    const int tg  = tid & 7;          // token group: tokens tg, tg+8, ..., tg+56
    const int cg  = tid >> 3;         // code group:  codes  cg, cg+32, ..., cg+224 (per chunk)

    const int n0  = blockIdx.x * TOK_PER_BLK;
    const int b   = n0 >> 12;                 // 4096 tokens per batch image
    const int hw0 = n0 & 4095;
    const float* zbase = batch + (size_t)b * (128 * 4096) + hw0;

    // ---- load z tile: zs[t][c], global reads coalesced along tokens ----
    for (int idx = tid; idx < TOK_PER_BLK * DIM; idx += 256) {
        int c = idx >> 6;
        int t = idx & 63;
        zs[t * ZSTRIDE + c] = zbase[(size_t)c * 4096 + t];
    }
    __syncthreads();

    // ---- znorm per token (plain mul+add to mirror sum-of-squares) ----
    if (tid < TOK_PER_BLK) {
        float s = 0.0f;
        const float* zr = zs + tid * ZSTRIDE;
        #pragma unroll 8
        for (int c = 0; c < DIM; c++)
            s = __fadd_rn(s, __fmul_rn(zr[c], zr[c]));
        zn[tid] = s;
    }

    int zrow[8], wrow[8];
    #pragma unroll
    for (int i = 0; i < 8; i++) zrow[i] = (tg + 8 * i) * ZSTRIDE;
    #pragma unroll
    for (int j = 0; j < 8; j++) wrow[j] = (cg + 32 * j) * ZSTRIDE;

    float bestv[8];
    int   besti[8];
    #pragma unroll
    for (int i = 0; i < 8; i++) { bestv[i] = CUDART_INF_F; besti[i] = 0; }

    float znr[8];
    bool znr_loaded = false;

    for (int chunk = 0; chunk < N_CHUNKS; chunk++) {
        const int cb = chunk * CODES_PER_CHUNK;
        __syncthreads();   // previous chunk fully consumed before overwriting ws/en

        // load 256-code chunk (float4, coalesced; codebook is L2-resident)
        for (int f = tid; f < CODES_PER_CHUNK * (DIM / 4); f += 256) {
            int code = f >> 5;       // 32 float4 per row
            int d4   = f & 31;
            float4 v = ((const float4*)(w + (size_t)(cb + code) * DIM))[d4];
            *(float4*)&ws[code * ZSTRIDE + d4 * 4] = v;
        }
        if (tid < CODES_PER_CHUNK) en[tid] = g_enorm[cb + tid];
        __syncthreads();

        if (!znr_loaded) {  // cache znorm in regs once (zn valid after first sync pair)
            #pragma unroll
            for (int i = 0; i < 8; i++) znr[i] = zn[tg + 8 * i];
            znr_loaded = true;
        }

        // ---- 8 tokens x 8 codes register tile, packed f32x2 along d ----
        unsigned long long acc[8][8];
        #pragma unroll
        for (int i = 0; i < 8; i++)
            #pragma unroll
            for (int j = 0; j < 8; j++) acc[i][j] = 0ull;

        #pragma unroll 2
        for (int d4 = 0; d4 < DIM / 4; d4++) {
            unsigned long long za0[8], za1[8];
            #pragma unroll
            for (int i = 0; i < 8; i++) {
                ulonglong2 v = *(const ulonglong2*)(zs + zrow[i] + d4 * 4);
                za0[i] = v.x; za1[i] = v.y;
            }
            #pragma unroll
            for (int j = 0; j < 8; j++) {
                ulonglong2 wv = *(const ulonglong2*)(ws + wrow[j] + d4 * 4);
                #pragma unroll
                for (int i = 0; i < 8; i++) {
                    acc[i][j] = ffma2(za0[i], wv.x, acc[i][j]);
                    acc[i][j] = ffma2(za1[i], wv.y, acc[i][j]);
                }
            }
        }

        // ---- fused distance + running argmin (exact reference rounding) ----
        #pragma unroll
        for (int j = 0; j < 8; j++) {
            const int code = cb + cg + 32 * j;
            const float ec = en[cg + 32 * j];
            #pragma unroll
            for (int i = 0; i < 8; i++) {
                float lo, hi;
                unpack2(acc[i][j], lo, hi);
                float dot = lo + hi;
                float s   = znr[i] + ec;          // (znorm + enorm), rounded
                float dis = fmaf(-2.0f, dot, s);  // == fl(s - 2*dot)
                if (dis < bestv[i]) { bestv[i] = dis; besti[i] = code; }
            }
        }
    }

    // ---- cross-thread argmin reduce (first-index tie-break) ----
    __syncthreads();
    #pragma unroll
    for (int i = 0; i < 8; i++) {
        int t = tg + 8 * i;
        rv[t * 32 + cg] = bestv[i];
        ri[t * 32 + cg] = besti[i];
    }
    __syncthreads();
    if (tid < TOK_PER_BLK) {
        float bv = rv[tid * 32];
        int   bi = ri[tid * 32];
        for (int c2 = 1; c2 < 32; c2++) {
            float v = rv[tid * 32 + c2];
            int   ii = ri[tid * 32 + c2];
            if (v < bv || (v == bv && ii < bi)) { bv = v; bi = ii; }
        }
        inds[tid] = bi;
    }
    __syncthreads();

    // ---- gather + straight-through output + loss partials ----
    double s1 = 0.0, s3 = 0.0;
    float* obase = out + (size_t)b * (128 * 4096) + hw0;
    for (int idx = tid; idx < TOK_PER_BLK * DIM; idx += 256) {
        int c = idx >> 6;
        int t = idx & 63;
        float z  = zs[t * ZSTRIDE + c];
        float q  = __ldg(&w[(size_t)inds[t] * DIM + c]);
        float dq = q - z;            // fl(z_q - z)
        float ov = z + dq;           // out = z + stop_grad(z_q - z)
        float d3 = z - ov;           // batch - out
        obase[(size_t)c * 4096 + t] = ov;
        float sq1 = dq * dq;         // squared in fp32 like the reference
        float sq3 = d3 * d3;
        s1 += (double)sq1;
        s3 += (double)sq3;
    }

    // block-reduce doubles (reuse ws; 8-byte aligned region)
    __syncthreads();
    double* red = (double*)ws;
    red[tid]       = s1;
    red[256 + tid] = s3;
    __syncthreads();
    #pragma unroll
    for (int stride = 128; stride > 0; stride >>= 1) {
        if (tid < stride) {
            red[tid]       += red[tid + stride];
            red[256 + tid] += red[256 + tid + stride];
        }
        __syncthreads();
    }
    if (tid == 0) {
        atomicAdd(&g_s1, red[0]);
        atomicAdd(&g_s3, red[256]);
    }
}

// ---------------- finalize: loss scalar ----------------
__global__ void vq_finalize(float* __restrict__ out, int out_size) {
    if (out_size <= TOT_ELEMS) return;
    const double inv = 1.0 / (double)TOT_ELEMS;
    float t1 = (float)(g_s1 * inv);       // mean((z_q - z)^2)  == term1 == term2
    float t3 = (float)(g_s3 * inv);       // mean((batch - out)^2)
    out[TOT_ELEMS] = (t1 + t1) + t3 * 50.0f;
}

// ---------------- launch ----------------
extern "C" void kernel_launch(void* const* d_in, const int* in_sizes, int n_in,
                              void* d_out, int out_size) {
    const float* batch = (const float*)d_in[0];
    const float* wq    = (const float*)d_in[1];
    if (n_in >= 2 && in_sizes[0] == NUM_CODES * DIM) {  // defensive: swapped order
        const float* t = batch; batch = wq; wq = t;
    }
    float* out = (float*)d_out;

    const int SMEM_BYTES =
        (TOK_PER_BLK * ZSTRIDE + CODES_PER_CHUNK * ZSTRIDE +
         TOK_PER_BLK + CODES_PER_CHUNK + TOK_PER_BLK) * (int)sizeof(float);

    cudaFuncSetAttribute(vq_main, cudaFuncAttributeMaxDynamicSharedMemorySize,
                         SMEM_BYTES);

    vq_prep<<<(NUM_CODES * 32 + 255) / 256, 256>>>(wq);
    vq_main<<<N_TOKENS / TOK_PER_BLK, 256, SMEM_BYTES>>>(batch, wq, out);
    vq_finalize<<<1, 1>>>(out, out_size);
}